// round 6
// baseline (speedup 1.0000x reference)
#include <cuda_runtime.h>
#include <math.h>
#include <stdint.h>

#define T_TOK 2048
#define NE 64
#define KTOP 8
#define SELK 4
#define HD 2048
#define FI 768
#define TWOF 1536
#define BM 128
#define MAXMT 192                      // sum ceil(cnt/128) <= 128 + 64
#define CAP (T_TOK * KTOP + NE * BM)   // 24576

// ---------------- scratch (device globals; no runtime allocation) ----------------
__device__ float d_topv[T_TOK * KTOP];
__device__ int   d_topi[T_TOK * KTOP];
__device__ int   d_rer[T_TOK * KTOP];
__device__ unsigned int d_pmask[2];
__device__ unsigned int d_smask[2];
__device__ int d_map[NE];
__device__ int d_counts[NE];
__device__ int d_padoff[NE];
__device__ int d_cursor[NE];
__device__ int d_tile_e[MAXMT];
__device__ int d_tile_base[MAXMT];
__device__ int d_tile_lim[MAXMT];
__device__ int d_nmt;
__device__ int d_totalpad;
__device__ int d_row_src[CAP];
__device__ float d_row_w[CAP];
__device__ int d_row_of[T_TOK * KTOP];
__device__ float d_hact[(size_t)CAP * FI];
__device__ float d_y[(size_t)CAP * HD];

// ---------------- tf32 helpers (legacy mma.sync path; tcgen05 not available
// through this build: ptxas target is sm_103 without the 'a' suffix) ----------
__device__ __forceinline__ uint32_t f2tf(float f) {
    uint32_t u;
    asm("cvt.rna.tf32.f32 %0, %1;" : "=r"(u) : "f"(f));
    return u;
}
__device__ __forceinline__ uint4 cvt4(float4 v) {
    uint4 r; r.x = f2tf(v.x); r.y = f2tf(v.y); r.z = f2tf(v.z); r.w = f2tf(v.w);
    return r;
}
__device__ __forceinline__ void mma_tf32(float* c, const uint32_t* a, uint32_t b0, uint32_t b1) {
    asm volatile(
        "mma.sync.aligned.m16n8k8.row.col.f32.tf32.tf32.f32 "
        "{%0,%1,%2,%3}, {%4,%5,%6,%7}, {%8,%9}, {%0,%1,%2,%3};\n"
        : "+f"(c[0]), "+f"(c[1]), "+f"(c[2]), "+f"(c[3])
        : "r"(a[0]), "r"(a[1]), "r"(a[2]), "r"(a[3]), "r"(b0), "r"(b1));
}

// ---------------- reset mutable state ----------------
__global__ void zero_kernel() {
    int i = threadIdx.x;
    if (i < NE) d_counts[i] = 0;
    if (i < 2) { d_pmask[i] = 0u; d_smask[i] = 0u; }
}

// ---------------- router ----------------
__global__ void router_kernel(const float* __restrict__ x, const float* __restrict__ gw) {
    __shared__ float sx[HD];
    __shared__ float sl[NE];
    int t = blockIdx.x;
    const float* xr = x + (size_t)t * HD;
    for (int i = threadIdx.x; i < HD; i += blockDim.x) sx[i] = xr[i];
    __syncthreads();

    int e   = threadIdx.x >> 2;
    int sub = threadIdx.x & 3;
    const float4* wp = (const float4*)(gw + (size_t)e * HD + sub * (HD / 4));
    const float4* xp = (const float4*)(sx + sub * (HD / 4));
    float s = 0.f;
#pragma unroll 4
    for (int i = 0; i < HD / 16; i++) {
        float4 a = xp[i]; float4 w = wp[i];
        s += a.x * w.x + a.y * w.y + a.z * w.z + a.w * w.w;
    }
    s += __shfl_xor_sync(0xffffffffu, s, 1);
    s += __shfl_xor_sync(0xffffffffu, s, 2);
    if (sub == 0) sl[e] = s;
    __syncthreads();

    if (threadIdx.x < 32) {
        int lane = threadIdx.x;
        float v0 = sl[lane], v1 = sl[lane + 32];
        float m = fmaxf(v0, v1);
        for (int off = 16; off; off >>= 1) m = fmaxf(m, __shfl_xor_sync(0xffffffffu, m, off));
        float e0 = expf(v0 - m), e1 = expf(v1 - m);
        float ss = e0 + e1;
        for (int off = 16; off; off >>= 1) ss += __shfl_xor_sync(0xffffffffu, ss, off);
        float p0 = e0 / ss, p1 = e1 / ss;

        float tv[KTOP]; int ti[KTOP];
#pragma unroll
        for (int k = 0; k < KTOP; k++) {
            float b; int bi;
            if (p0 >= p1) { b = p0; bi = lane; } else { b = p1; bi = lane + 32; }
            for (int off = 16; off; off >>= 1) {
                float ob = __shfl_xor_sync(0xffffffffu, b, off);
                int obi  = __shfl_xor_sync(0xffffffffu, bi, off);
                if (ob > b || (ob == b && obi < bi)) { b = ob; bi = obi; }
            }
            tv[k] = b; ti[k] = bi;
            if (bi < 32) { if (lane == bi) p0 = -1.f; }
            else         { if (lane == bi - 32) p1 = -1.f; }
        }
        if (lane == 0) {
            float tsum = 0.f;
#pragma unroll
            for (int k = 0; k < KTOP; k++) tsum += tv[k];
            tsum = fmaxf(tsum, 1e-12f);
#pragma unroll
            for (int k = 0; k < KTOP; k++) {
                d_topv[t * KTOP + k] = tv[k] / tsum;
                d_topi[t * KTOP + k] = ti[k];
                int b = ti[k];
                if (k < SELK) atomicOr(&d_pmask[b >> 5], 1u << (b & 31));
                else          atomicOr(&d_smask[b >> 5], 1u << (b & 31));
            }
        }
    }
}

// ---------------- SERE mapping ----------------
__global__ void mapping_kernel(const float* __restrict__ sim) {
    int e = threadIdx.x;
    if (e >= NE) return;
    unsigned pm0 = d_pmask[0], pm1 = d_pmask[1];
    unsigned sm0 = d_smask[0], sm1 = d_smask[1];
    bool prim = (e < 32) ? ((pm0 >> e) & 1) : ((pm1 >> (e - 32)) & 1);
    bool sec  = (e < 32) ? ((sm0 >> e) & 1) : ((sm1 >> (e - 32)) & 1);
    int best = 0; float bs = -INFINITY;
    for (int p = 0; p < NE; p++) {
        bool pp = (p < 32) ? ((pm0 >> p) & 1) : ((pm1 >> (p - 32)) & 1);
        if (!pp) continue;
        float v = (p == e) ? 1.0f : sim[e * NE + p];
        if (v > bs) { bs = v; best = p; }
    }
    int mp = e;
    if (sec && !prim && bs >= 0.5f) mp = best;
    d_map[e] = mp;
}

// ---------------- reroute + counts ----------------
__global__ void reroute_kernel() {
    int a = blockIdx.x * blockDim.x + threadIdx.x;
    if (a >= T_TOK * KTOP) return;
    int k = a & 7;
    int e0 = d_topi[a];
    int e = (k < SELK) ? e0 : d_map[e0];
    d_rer[a] = e;
    atomicAdd(&d_counts[e], 1);
}

// ---------------- tile table (BM=128 padding) ----------------
__global__ void build_tiles_kernel() {
    if (threadIdx.x != 0 || blockIdx.x != 0) return;
    int off = 0, nt = 0;
    for (int e = 0; e < NE; e++) {
        d_padoff[e] = off;
        d_cursor[e] = 0;
        int c = d_counts[e];
        int mt = (c + BM - 1) / BM;
        for (int i = 0; i < mt; i++) {
            d_tile_e[nt] = e;
            d_tile_base[nt] = off + i * BM;
            int lm = c - i * BM; if (lm > BM) lm = BM;
            d_tile_lim[nt] = lm;
            nt++;
        }
        off += mt * BM;
    }
    d_nmt = nt;
    d_totalpad = off;
}

// ---------------- scatter ----------------
__global__ void scatter_kernel() {
    int a = blockIdx.x * blockDim.x + threadIdx.x;
    if (a >= T_TOK * KTOP) return;
    int e = d_rer[a];
    int pos = d_padoff[e] + atomicAdd(&d_cursor[e], 1);
    d_row_src[pos] = a >> 3;
    d_row_w[pos] = d_topv[a];
    d_row_of[a] = pos;
}

// ======================================================================
// GEMM1 (tf32 mma.sync) + fused SwiGLU.
// CTA: 128 token-rows x (64 gate cols + matching 64 up cols).
// 8 warps: wm = warp>>1 (4 x 32 rows), wn = warp&1 (2 x 32 cols).
// ======================================================================
__global__ __launch_bounds__(256, 2) void gemm1_kernel(const float* __restrict__ x,
                                                       const float* __restrict__ gup) {
    int bx = blockIdx.x;
    if (bx >= d_nmt) return;
    int e = d_tile_e[bx], base = d_tile_base[bx], lim = d_tile_lim[bx];
    int n0 = blockIdx.y * 64;          // gate column base in [0, 768)

    __shared__ __align__(16) uint32_t As[2][128][20];
    __shared__ __align__(16) uint32_t Bs[2][128][20];   // rows 0-63 gate, 64-127 up
    __shared__ int srow[128];

    int tid = threadIdx.x;
    if (tid < 128) srow[tid] = (tid < lim) ? d_row_src[base + tid] : -1;
    __syncthreads();

    int lrow = tid >> 1;               // 0..127
    int lk = (tid & 1) * 8;            // 0 or 8
    int sA = srow[lrow];
    const float* aptr = (sA >= 0) ? (x + (size_t)sA * HD + lk) : (const float*)0;
    int br = (lrow < 64) ? (n0 + lrow) : (FI + n0 + (lrow - 64));
    const float* bptr = gup + ((size_t)e * TWOF + br) * HD + lk;

    int warp = tid >> 5, lane = tid & 31;
    int wm = warp >> 1, wn = warp & 1;
    int g = lane >> 2, tg = lane & 3;

    float cg[2][4][4] = {};
    float cu[2][4][4] = {};

    const float4 z4 = make_float4(0.f, 0.f, 0.f, 0.f);
    float4 ra0, ra1, rb0, rb1;
    ra0 = aptr ? ((const float4*)aptr)[0] : z4;
    ra1 = aptr ? ((const float4*)aptr)[1] : z4;
    rb0 = ((const float4*)bptr)[0];
    rb1 = ((const float4*)bptr)[1];
    *(uint4*)&As[0][lrow][lk]     = cvt4(ra0);
    *(uint4*)&As[0][lrow][lk + 4] = cvt4(ra1);
    *(uint4*)&Bs[0][lrow][lk]     = cvt4(rb0);
    *(uint4*)&Bs[0][lrow][lk + 4] = cvt4(rb1);
    __syncthreads();

    int buf = 0;
    const int NIT = HD / 16;           // 128
    for (int it = 0; it < NIT; it++) {
        if (it + 1 < NIT) {
            int kn = (it + 1) * 16;
            ra0 = aptr ? ((const float4*)(aptr + kn))[0] : z4;
            ra1 = aptr ? ((const float4*)(aptr + kn))[1] : z4;
            rb0 = ((const float4*)(bptr + kn))[0];
            rb1 = ((const float4*)(bptr + kn))[1];
        }
#pragma unroll
        for (int kk = 0; kk < 16; kk += 8) {
            uint32_t af[2][4];
#pragma unroll
            for (int mi = 0; mi < 2; mi++) {
                int r = wm * 32 + mi * 16;
                af[mi][0] = As[buf][r + g][kk + tg];
                af[mi][1] = As[buf][r + g + 8][kk + tg];
                af[mi][2] = As[buf][r + g][kk + tg + 4];
                af[mi][3] = As[buf][r + g + 8][kk + tg + 4];
            }
#pragma unroll
            for (int ni = 0; ni < 4; ni++) {
                int c = wn * 32 + ni * 8 + g;
                uint32_t b0 = Bs[buf][c][kk + tg],       b1 = Bs[buf][c][kk + tg + 4];
                uint32_t u0 = Bs[buf][64 + c][kk + tg],  u1 = Bs[buf][64 + c][kk + tg + 4];
#pragma unroll
                for (int mi = 0; mi < 2; mi++) {
                    mma_tf32(cg[mi][ni], af[mi], b0, b1);
                    mma_tf32(cu[mi][ni], af[mi], u0, u1);
                }
            }
        }
        if (it + 1 < NIT) {
            int d = buf ^ 1;
            *(uint4*)&As[d][lrow][lk]     = cvt4(ra0);
            *(uint4*)&As[d][lrow][lk + 4] = cvt4(ra1);
            *(uint4*)&Bs[d][lrow][lk]     = cvt4(rb0);
            *(uint4*)&Bs[d][lrow][lk + 4] = cvt4(rb1);
        }
        __syncthreads();
        buf ^= 1;
    }

    // fused SwiGLU epilogue
#pragma unroll
    for (int mi = 0; mi < 2; mi++) {
#pragma unroll
        for (int half = 0; half < 2; half++) {
            int row = wm * 32 + mi * 16 + g + half * 8;
            if (row < lim) {
                float* dst = d_hact + (size_t)(base + row) * FI + n0 + wn * 32;
#pragma unroll
                for (int ni = 0; ni < 4; ni++) {
                    float g0 = cg[mi][ni][half * 2 + 0], g1 = cg[mi][ni][half * 2 + 1];
                    float u0 = cu[mi][ni][half * 2 + 0], u1 = cu[mi][ni][half * 2 + 1];
                    float h0 = g0 / (1.f + expf(-g0)) * u0;
                    float h1 = g1 / (1.f + expf(-g1)) * u1;
                    *(float2*)(dst + ni * 8 + tg * 2) = make_float2(h0, h1);
                }
            }
        }
    }
}

// ======================================================================
// GEMM2 (tf32 mma.sync): y[r, n0:n0+128] = w[r] * (hact[r] @ down[e]^T)
// CTA: 128 rows x 128 cols. 8 warps: wm = warp>>1 (32 rows), wn = warp&1 (64 cols).
// ======================================================================
__global__ __launch_bounds__(256, 2) void gemm2_kernel(const float* __restrict__ dwn) {
    int bx = blockIdx.x;
    if (bx >= d_nmt) return;
    int e = d_tile_e[bx], base = d_tile_base[bx], lim = d_tile_lim[bx];
    int n0 = blockIdx.y * 128;         // output column in [0, 2048)

    __shared__ __align__(16) uint32_t As[2][128][20];
    __shared__ __align__(16) uint32_t Bs[2][128][20];

    int tid = threadIdx.x;
    int lrow = tid >> 1;
    int lk = (tid & 1) * 8;
    const float* aptr = d_hact + (size_t)(base + lrow) * FI + lk;
    const float* bptr = dwn + ((size_t)e * HD + n0 + lrow) * FI + lk;

    int warp = tid >> 5, lane = tid & 31;
    int wm = warp >> 1, wn = warp & 1;
    int g = lane >> 2, tg = lane & 3;

    float cc[2][8][4] = {};

    float4 ra0, ra1, rb0, rb1;
    ra0 = ((const float4*)aptr)[0];
    ra1 = ((const float4*)aptr)[1];
    rb0 = ((const float4*)bptr)[0];
    rb1 = ((const float4*)bptr)[1];
    *(uint4*)&As[0][lrow][lk]     = cvt4(ra0);
    *(uint4*)&As[0][lrow][lk + 4] = cvt4(ra1);
    *(uint4*)&Bs[0][lrow][lk]     = cvt4(rb0);
    *(uint4*)&Bs[0][lrow][lk + 4] = cvt4(rb1);
    __syncthreads();

    int buf = 0;
    const int NIT = FI / 16;           // 48
    for (int it = 0; it < NIT; it++) {
        if (it + 1 < NIT) {
            int kn = (it + 1) * 16;
            ra0 = ((const float4*)(aptr + kn))[0];
            ra1 = ((const float4*)(aptr + kn))[1];
            rb0 = ((const float4*)(bptr + kn))[0];
            rb1 = ((const float4*)(bptr + kn))[1];
        }
#pragma unroll
        for (int kk = 0; kk < 16; kk += 8) {
            uint32_t af[2][4];
#pragma unroll
            for (int mi = 0; mi < 2; mi++) {
                int r = wm * 32 + mi * 16;
                af[mi][0] = As[buf][r + g][kk + tg];
                af[mi][1] = As[buf][r + g + 8][kk + tg];
                af[mi][2] = As[buf][r + g][kk + tg + 4];
                af[mi][3] = As[buf][r + g + 8][kk + tg + 4];
            }
#pragma unroll
            for (int ni = 0; ni < 8; ni++) {
                int c = wn * 64 + ni * 8 + g;
                uint32_t b0 = Bs[buf][c][kk + tg], b1 = Bs[buf][c][kk + tg + 4];
#pragma unroll
                for (int mi = 0; mi < 2; mi++)
                    mma_tf32(cc[mi][ni], af[mi], b0, b1);
            }
        }
        if (it + 1 < NIT) {
            int d = buf ^ 1;
            *(uint4*)&As[d][lrow][lk]     = cvt4(ra0);
            *(uint4*)&As[d][lrow][lk + 4] = cvt4(ra1);
            *(uint4*)&Bs[d][lrow][lk]     = cvt4(rb0);
            *(uint4*)&Bs[d][lrow][lk + 4] = cvt4(rb1);
        }
        __syncthreads();
        buf ^= 1;
    }

#pragma unroll
    for (int mi = 0; mi < 2; mi++) {
#pragma unroll
        for (int half = 0; half < 2; half++) {
            int row = wm * 32 + mi * 16 + g + half * 8;
            if (row < lim) {
                float w = d_row_w[base + row];
                float* dst = d_y + (size_t)(base + row) * HD + n0 + wn * 64;
#pragma unroll
                for (int ni = 0; ni < 8; ni++) {
                    float v0 = cc[mi][ni][half * 2 + 0] * w;
                    float v1 = cc[mi][ni][half * 2 + 1] * w;
                    *(float2*)(dst + ni * 8 + tg * 2) = make_float2(v0, v1);
                }
            }
        }
    }
}

// ---------------- deterministic combine ----------------
__global__ void combine_kernel(float* __restrict__ out) {
    int t = blockIdx.x;
    __shared__ int rows[KTOP];
    if (threadIdx.x < KTOP) rows[threadIdx.x] = d_row_of[t * KTOP + threadIdx.x];
    __syncthreads();
    for (int h = threadIdx.x; h < HD; h += blockDim.x) {
        float s = 0.f;
#pragma unroll
        for (int k = 0; k < KTOP; k++) s += d_y[(size_t)rows[k] * HD + h];
        out[(size_t)t * HD + h] = s;
    }
}

// ---------------- launch ----------------
extern "C" void kernel_launch(void* const* d_in, const int* in_sizes, int n_in,
                              void* d_out, int out_size) {
    const float* x   = (const float*)d_in[0];   // [1, 2048, 2048]
    const float* gw  = (const float*)d_in[1];   // [64, 2048]
    const float* gup = (const float*)d_in[2];   // [64, 1536, 2048]
    const float* dwn = (const float*)d_in[3];   // [64, 2048, 768]
    const float* sim = (const float*)d_in[4];   // [64, 64]
    float* out = (float*)d_out;

    zero_kernel<<<1, 64>>>();
    router_kernel<<<T_TOK, 256>>>(x, gw);
    mapping_kernel<<<1, 64>>>(sim);
    reroute_kernel<<<(T_TOK * KTOP + 255) / 256, 256>>>();
    build_tiles_kernel<<<1, 1>>>();
    scatter_kernel<<<(T_TOK * KTOP + 255) / 256, 256>>>();
    gemm1_kernel<<<dim3(MAXMT, FI / 64), 256>>>(x, gup);
    gemm2_kernel<<<dim3(MAXMT, HD / 128), 256>>>(dwn);
    combine_kernel<<<T_TOK, 256>>>(out);
}

// round 7
// speedup vs baseline: 1.4279x; 1.4279x over previous
#include <cuda_runtime.h>
#include <math.h>
#include <stdint.h>

#define T_TOK 2048
#define NE 64
#define KTOP 8
#define SELK 4
#define HD 2048
#define FI 768
#define TWOF 1536
#define BM 64
#define MAXMT 320            // sum ceil(cnt/64) <= 16384/64 + 64
#define CAP 20480            // 16384 + 64*64 padded rows

// ---------------- scratch (device globals; no runtime allocation) ----------------
__device__ float d_topv[T_TOK * KTOP];
__device__ int   d_topi[T_TOK * KTOP];
__device__ int   d_rer[T_TOK * KTOP];
__device__ unsigned int d_pmask[2];
__device__ unsigned int d_smask[2];
__device__ int d_map[NE];
__device__ int d_counts[NE];
__device__ int d_padoff[NE];
__device__ int d_cursor[NE];
__device__ int d_tile_e[MAXMT];
__device__ int d_tile_base[MAXMT];
__device__ int d_tile_lim[MAXMT];
__device__ int d_nmt;
__device__ int d_totalpad;
__device__ int d_row_src[CAP];
__device__ float d_row_w[CAP];
__device__ int d_row_of[T_TOK * KTOP];
__device__ float d_hact[(size_t)CAP * FI];
__device__ float d_y[(size_t)CAP * HD];

// ---------------- fp16 helpers (legacy mma.sync path; tcgen05 unavailable:
// harness ptxas target is sm_103 without the 'a' suffix) ----------------------
__device__ __forceinline__ uint32_t packh2(float lo, float hi) {
    uint32_t u;
    asm("cvt.rn.f16x2.f32 %0, %1, %2;" : "=r"(u) : "f"(hi), "f"(lo));
    return u;
}
__device__ __forceinline__ uint2 cvt4h(float4 v) {
    return make_uint2(packh2(v.x, v.y), packh2(v.z, v.w));
}
__device__ __forceinline__ void mma_f16(float* c, const uint32_t* a, uint32_t b0, uint32_t b1) {
    asm volatile(
        "mma.sync.aligned.m16n8k16.row.col.f32.f16.f16.f32 "
        "{%0,%1,%2,%3}, {%4,%5,%6,%7}, {%8,%9}, {%0,%1,%2,%3};\n"
        : "+f"(c[0]), "+f"(c[1]), "+f"(c[2]), "+f"(c[3])
        : "r"(a[0]), "r"(a[1]), "r"(a[2]), "r"(a[3]), "r"(b0), "r"(b1));
}

// ---------------- reset mutable state ----------------
__global__ void zero_kernel() {
    int i = threadIdx.x;
    if (i < NE) d_counts[i] = 0;
    if (i < 2) { d_pmask[i] = 0u; d_smask[i] = 0u; }
}

// ---------------- router ----------------
__global__ void router_kernel(const float* __restrict__ x, const float* __restrict__ gw) {
    __shared__ float sx[HD];
    __shared__ float sl[NE];
    int t = blockIdx.x;
    const float* xr = x + (size_t)t * HD;
    for (int i = threadIdx.x; i < HD; i += blockDim.x) sx[i] = xr[i];
    __syncthreads();

    int e   = threadIdx.x >> 2;
    int sub = threadIdx.x & 3;
    const float4* wp = (const float4*)(gw + (size_t)e * HD + sub * (HD / 4));
    const float4* xp = (const float4*)(sx + sub * (HD / 4));
    float s = 0.f;
#pragma unroll 4
    for (int i = 0; i < HD / 16; i++) {
        float4 a = xp[i]; float4 w = wp[i];
        s += a.x * w.x + a.y * w.y + a.z * w.z + a.w * w.w;
    }
    s += __shfl_xor_sync(0xffffffffu, s, 1);
    s += __shfl_xor_sync(0xffffffffu, s, 2);
    if (sub == 0) sl[e] = s;
    __syncthreads();

    if (threadIdx.x < 32) {
        int lane = threadIdx.x;
        float v0 = sl[lane], v1 = sl[lane + 32];
        float m = fmaxf(v0, v1);
        for (int off = 16; off; off >>= 1) m = fmaxf(m, __shfl_xor_sync(0xffffffffu, m, off));
        float e0 = expf(v0 - m), e1 = expf(v1 - m);
        float ss = e0 + e1;
        for (int off = 16; off; off >>= 1) ss += __shfl_xor_sync(0xffffffffu, ss, off);
        float p0 = e0 / ss, p1 = e1 / ss;

        float tv[KTOP]; int ti[KTOP];
#pragma unroll
        for (int k = 0; k < KTOP; k++) {
            float b; int bi;
            if (p0 >= p1) { b = p0; bi = lane; } else { b = p1; bi = lane + 32; }
            for (int off = 16; off; off >>= 1) {
                float ob = __shfl_xor_sync(0xffffffffu, b, off);
                int obi  = __shfl_xor_sync(0xffffffffu, bi, off);
                if (ob > b || (ob == b && obi < bi)) { b = ob; bi = obi; }
            }
            tv[k] = b; ti[k] = bi;
            if (bi < 32) { if (lane == bi) p0 = -1.f; }
            else         { if (lane == bi - 32) p1 = -1.f; }
        }
        if (lane == 0) {
            float tsum = 0.f;
#pragma unroll
            for (int k = 0; k < KTOP; k++) tsum += tv[k];
            tsum = fmaxf(tsum, 1e-12f);
#pragma unroll
            for (int k = 0; k < KTOP; k++) {
                d_topv[t * KTOP + k] = tv[k] / tsum;
                d_topi[t * KTOP + k] = ti[k];
                int b = ti[k];
                if (k < SELK) atomicOr(&d_pmask[b >> 5], 1u << (b & 31));
                else          atomicOr(&d_smask[b >> 5], 1u << (b & 31));
            }
        }
    }
}

// ---------------- SERE mapping ----------------
__global__ void mapping_kernel(const float* __restrict__ sim) {
    int e = threadIdx.x;
    if (e >= NE) return;
    unsigned pm0 = d_pmask[0], pm1 = d_pmask[1];
    unsigned sm0 = d_smask[0], sm1 = d_smask[1];
    bool prim = (e < 32) ? ((pm0 >> e) & 1) : ((pm1 >> (e - 32)) & 1);
    bool sec  = (e < 32) ? ((sm0 >> e) & 1) : ((sm1 >> (e - 32)) & 1);
    int best = 0; float bs = -INFINITY;
    for (int p = 0; p < NE; p++) {
        bool pp = (p < 32) ? ((pm0 >> p) & 1) : ((pm1 >> (p - 32)) & 1);
        if (!pp) continue;
        float v = (p == e) ? 1.0f : sim[e * NE + p];
        if (v > bs) { bs = v; best = p; }
    }
    int mp = e;
    if (sec && !prim && bs >= 0.5f) mp = best;
    d_map[e] = mp;
}

// ---------------- reroute + counts ----------------
__global__ void reroute_kernel() {
    int a = blockIdx.x * blockDim.x + threadIdx.x;
    if (a >= T_TOK * KTOP) return;
    int k = a & 7;
    int e0 = d_topi[a];
    int e = (k < SELK) ? e0 : d_map[e0];
    d_rer[a] = e;
    atomicAdd(&d_counts[e], 1);
}

// ---------------- tile table ----------------
__global__ void build_tiles_kernel() {
    if (threadIdx.x != 0 || blockIdx.x != 0) return;
    int off = 0, nt = 0;
    for (int e = 0; e < NE; e++) {
        d_padoff[e] = off;
        d_cursor[e] = 0;
        int c = d_counts[e];
        int mt = (c + BM - 1) / BM;
        for (int i = 0; i < mt; i++) {
            d_tile_e[nt] = e;
            d_tile_base[nt] = off + i * BM;
            int lm = c - i * BM; if (lm > BM) lm = BM;
            d_tile_lim[nt] = lm;
            nt++;
        }
        off += mt * BM;
    }
    d_nmt = nt;
    d_totalpad = off;
}

// ---------------- scatter ----------------
__global__ void scatter_kernel() {
    int a = blockIdx.x * blockDim.x + threadIdx.x;
    if (a >= T_TOK * KTOP) return;
    int e = d_rer[a];
    int pos = d_padoff[e] + atomicAdd(&d_cursor[e], 1);
    d_row_src[pos] = a >> 3;
    d_row_w[pos] = d_topv[a];
    d_row_of[a] = pos;
}

// ======================================================================
// GEMM1 (fp16 mma.sync m16n8k16, fp32 accum) + fused SwiGLU.
// CTA: 64 token-rows x (64 gate cols + matching 64 up cols), 4 warps,
// warp tile 32 rows x 32 gate + 32 up cols. BK = 32 floats per stage.
// SMEM element = half2 (one uint per 2 k's), row = 16 uints padded to 20.
// ======================================================================
__global__ __launch_bounds__(128) void gemm1_kernel(const float* __restrict__ x,
                                                    const float* __restrict__ gup) {
    int bx = blockIdx.x;
    if (bx >= d_nmt) return;
    int e = d_tile_e[bx], base = d_tile_base[bx], lim = d_tile_lim[bx];
    int n0 = blockIdx.y * 64;          // gate column base in [0, 768)

    __shared__ __align__(16) uint32_t As[2][64][20];    // 64 rows x 16 kpairs
    __shared__ __align__(16) uint32_t Bs[2][128][20];   // rows 0-63 gate, 64-127 up
    __shared__ int srow[64];

    int tid = threadIdx.x;
    if (tid < 64) srow[tid] = (tid < lim) ? d_row_src[base + tid] : -1;
    __syncthreads();

    int lkq = tid & 3;                 // quarter of 32 k-floats: 8 floats each
    int r0 = tid >> 2;                 // 0..31
    const float* aptr[2];
#pragma unroll
    for (int i = 0; i < 2; i++) {
        int s = srow[r0 + i * 32];
        aptr[i] = (s >= 0) ? (x + (size_t)s * HD + lkq * 8) : (const float*)0;
    }
    const float* bptr[4];
#pragma unroll
    for (int i = 0; i < 4; i++) {
        int row = r0 + i * 32;
        int br = (row < 64) ? (n0 + row) : (FI + n0 + (row - 64));
        bptr[i] = gup + ((size_t)e * TWOF + br) * HD + lkq * 8;
    }

    int warp = tid >> 5, lane = tid & 31;
    int wm = warp >> 1, wn = warp & 1;
    int g = lane >> 2, tg = lane & 3;

    float cg[2][4][4] = {};
    float cu[2][4][4] = {};

    const float4 z4 = make_float4(0.f, 0.f, 0.f, 0.f);
    float4 ra[2][2], rb[4][2];
#pragma unroll
    for (int i = 0; i < 2; i++) {
        ra[i][0] = aptr[i] ? ((const float4*)aptr[i])[0] : z4;
        ra[i][1] = aptr[i] ? ((const float4*)aptr[i])[1] : z4;
    }
#pragma unroll
    for (int i = 0; i < 4; i++) {
        rb[i][0] = ((const float4*)bptr[i])[0];
        rb[i][1] = ((const float4*)bptr[i])[1];
    }
#pragma unroll
    for (int i = 0; i < 2; i++) {
        uint2 p0 = cvt4h(ra[i][0]), p1 = cvt4h(ra[i][1]);
        *(uint4*)&As[0][r0 + i * 32][lkq * 4] = make_uint4(p0.x, p0.y, p1.x, p1.y);
    }
#pragma unroll
    for (int i = 0; i < 4; i++) {
        uint2 p0 = cvt4h(rb[i][0]), p1 = cvt4h(rb[i][1]);
        *(uint4*)&Bs[0][r0 + i * 32][lkq * 4] = make_uint4(p0.x, p0.y, p1.x, p1.y);
    }
    __syncthreads();

    int buf = 0;
    const int NIT = HD / 32;           // 64
    for (int it = 0; it < NIT; it++) {
        if (it + 1 < NIT) {
            int kn = (it + 1) * 32;
#pragma unroll
            for (int i = 0; i < 2; i++) {
                ra[i][0] = aptr[i] ? ((const float4*)(aptr[i] + kn))[0] : z4;
                ra[i][1] = aptr[i] ? ((const float4*)(aptr[i] + kn))[1] : z4;
            }
#pragma unroll
            for (int i = 0; i < 4; i++) {
                rb[i][0] = ((const float4*)(bptr[i] + kn))[0];
                rb[i][1] = ((const float4*)(bptr[i] + kn))[1];
            }
        }
#pragma unroll
        for (int kk = 0; kk < 16; kk += 8) {           // two k16 steps per stage
            uint32_t af[2][4];
#pragma unroll
            for (int mi = 0; mi < 2; mi++) {
                int r = wm * 32 + mi * 16;
                af[mi][0] = As[buf][r + g][kk + tg];
                af[mi][1] = As[buf][r + g + 8][kk + tg];
                af[mi][2] = As[buf][r + g][kk + tg + 4];
                af[mi][3] = As[buf][r + g + 8][kk + tg + 4];
            }
#pragma unroll
            for (int ni = 0; ni < 4; ni++) {
                int c = wn * 32 + ni * 8 + g;
                uint32_t b0 = Bs[buf][c][kk + tg],       b1 = Bs[buf][c][kk + tg + 4];
                uint32_t u0 = Bs[buf][64 + c][kk + tg],  u1 = Bs[buf][64 + c][kk + tg + 4];
#pragma unroll
                for (int mi = 0; mi < 2; mi++) {
                    mma_f16(cg[mi][ni], af[mi], b0, b1);
                    mma_f16(cu[mi][ni], af[mi], u0, u1);
                }
            }
        }
        if (it + 1 < NIT) {
            int d = buf ^ 1;
#pragma unroll
            for (int i = 0; i < 2; i++) {
                uint2 p0 = cvt4h(ra[i][0]), p1 = cvt4h(ra[i][1]);
                *(uint4*)&As[d][r0 + i * 32][lkq * 4] = make_uint4(p0.x, p0.y, p1.x, p1.y);
            }
#pragma unroll
            for (int i = 0; i < 4; i++) {
                uint2 p0 = cvt4h(rb[i][0]), p1 = cvt4h(rb[i][1]);
                *(uint4*)&Bs[d][r0 + i * 32][lkq * 4] = make_uint4(p0.x, p0.y, p1.x, p1.y);
            }
        }
        __syncthreads();
        buf ^= 1;
    }

    // fused SwiGLU epilogue
#pragma unroll
    for (int mi = 0; mi < 2; mi++) {
#pragma unroll
        for (int half = 0; half < 2; half++) {
            int row = wm * 32 + mi * 16 + g + half * 8;
            if (row < lim) {
                float* dst = d_hact + (size_t)(base + row) * FI + n0 + wn * 32;
#pragma unroll
                for (int ni = 0; ni < 4; ni++) {
                    float g0 = cg[mi][ni][half * 2 + 0], g1 = cg[mi][ni][half * 2 + 1];
                    float u0 = cu[mi][ni][half * 2 + 0], u1 = cu[mi][ni][half * 2 + 1];
                    float h0 = g0 / (1.f + expf(-g0)) * u0;
                    float h1 = g1 / (1.f + expf(-g1)) * u1;
                    *(float2*)(dst + ni * 8 + tg * 2) = make_float2(h0, h1);
                }
            }
        }
    }
}

// ======================================================================
// GEMM2 (fp16 mma.sync): y[r, n0:n0+64] = w[r] * (hact[r] @ down[e]^T)
// CTA: 64 rows x 64 cols, 4 warps, warp tile 32x32. BK = 32 floats.
// ======================================================================
__global__ __launch_bounds__(128) void gemm2_kernel(const float* __restrict__ dwn) {
    int bx = blockIdx.x;
    if (bx >= d_nmt) return;
    int e = d_tile_e[bx], base = d_tile_base[bx], lim = d_tile_lim[bx];
    int n0 = blockIdx.y * 64;          // output column in [0, 2048)

    __shared__ __align__(16) uint32_t As[2][64][20];
    __shared__ __align__(16) uint32_t Bs[2][64][20];

    int tid = threadIdx.x;
    int lkq = tid & 3;
    int r0 = tid >> 2;
    const float* aptr[2];
#pragma unroll
    for (int i = 0; i < 2; i++)
        aptr[i] = d_hact + (size_t)(base + r0 + i * 32) * FI + lkq * 8;
    const float* bptr[2];
#pragma unroll
    for (int i = 0; i < 2; i++)
        bptr[i] = dwn + ((size_t)e * HD + n0 + r0 + i * 32) * FI + lkq * 8;

    int warp = tid >> 5, lane = tid & 31;
    int wm = warp >> 1, wn = warp & 1;
    int g = lane >> 2, tg = lane & 3;

    float cc[2][4][4] = {};

    float4 ra[2][2], rb[2][2];
#pragma unroll
    for (int i = 0; i < 2; i++) {
        ra[i][0] = ((const float4*)aptr[i])[0];
        ra[i][1] = ((const float4*)aptr[i])[1];
        rb[i][0] = ((const float4*)bptr[i])[0];
        rb[i][1] = ((const float4*)bptr[i])[1];
    }
#pragma unroll
    for (int i = 0; i < 2; i++) {
        uint2 a0 = cvt4h(ra[i][0]), a1 = cvt4h(ra[i][1]);
        uint2 b0 = cvt4h(rb[i][0]), b1 = cvt4h(rb[i][1]);
        *(uint4*)&As[0][r0 + i * 32][lkq * 4] = make_uint4(a0.x, a0.y, a1.x, a1.y);
        *(uint4*)&Bs[0][r0 + i * 32][lkq * 4] = make_uint4(b0.x, b0.y, b1.x, b1.y);
    }
    __syncthreads();

    int buf = 0;
    const int NIT = FI / 32;           // 24
    for (int it = 0; it < NIT; it++) {
        if (it + 1 < NIT) {
            int kn = (it + 1) * 32;
#pragma unroll
            for (int i = 0; i < 2; i++) {
                ra[i][0] = ((const float4*)(aptr[i] + kn))[0];
                ra[i][1] = ((const float4*)(aptr[i] + kn))[1];
                rb[i][0] = ((const float4*)(bptr[i] + kn))[0];
                rb[i][1] = ((const float4*)(bptr[i] + kn))[1];
            }
        }
#pragma unroll
        for (int kk = 0; kk < 16; kk += 8) {
            uint32_t af[2][4];
#pragma unroll
            for (int mi = 0; mi < 2; mi++) {
                int r = wm * 32 + mi * 16;
                af[mi][0] = As[buf][r + g][kk + tg];
                af[mi][1] = As[buf][r + g + 8][kk + tg];
                af[mi][2] = As[buf][r + g][kk + tg + 4];
                af[mi][3] = As[buf][r + g + 8][kk + tg + 4];
            }
#pragma unroll
            for (int ni = 0; ni < 4; ni++) {
                int c = wn * 32 + ni * 8 + g;
                uint32_t b0 = Bs[buf][c][kk + tg], b1 = Bs[buf][c][kk + tg + 4];
#pragma unroll
                for (int mi = 0; mi < 2; mi++)
                    mma_f16(cc[mi][ni], af[mi], b0, b1);
            }
        }
        if (it + 1 < NIT) {
            int d = buf ^ 1;
#pragma unroll
            for (int i = 0; i < 2; i++) {
                uint2 a0 = cvt4h(ra[i][0]), a1 = cvt4h(ra[i][1]);
                uint2 b0 = cvt4h(rb[i][0]), b1 = cvt4h(rb[i][1]);
                *(uint4*)&As[d][r0 + i * 32][lkq * 4] = make_uint4(a0.x, a0.y, a1.x, a1.y);
                *(uint4*)&Bs[d][r0 + i * 32][lkq * 4] = make_uint4(b0.x, b0.y, b1.x, b1.y);
            }
        }
        __syncthreads();
        buf ^= 1;
    }

#pragma unroll
    for (int mi = 0; mi < 2; mi++) {
#pragma unroll
        for (int half = 0; half < 2; half++) {
            int row = wm * 32 + mi * 16 + g + half * 8;
            if (row < lim) {
                float w = d_row_w[base + row];
                float* dst = d_y + (size_t)(base + row) * HD + n0 + wn * 32;
#pragma unroll
                for (int ni = 0; ni < 4; ni++) {
                    float v0 = cc[mi][ni][half * 2 + 0] * w;
                    float v1 = cc[mi][ni][half * 2 + 1] * w;
                    *(float2*)(dst + ni * 8 + tg * 2) = make_float2(v0, v1);
                }
            }
        }
    }
}

// ---------------- deterministic combine ----------------
__global__ void combine_kernel(float* __restrict__ out) {
    int t = blockIdx.x;
    __shared__ int rows[KTOP];
    if (threadIdx.x < KTOP) rows[threadIdx.x] = d_row_of[t * KTOP + threadIdx.x];
    __syncthreads();
    for (int h = threadIdx.x; h < HD; h += blockDim.x) {
        float s = 0.f;
#pragma unroll
        for (int k = 0; k < KTOP; k++) s += d_y[(size_t)rows[k] * HD + h];
        out[(size_t)t * HD + h] = s;
    }
}

// ---------------- launch ----------------
extern "C" void kernel_launch(void* const* d_in, const int* in_sizes, int n_in,
                              void* d_out, int out_size) {
    const float* x   = (const float*)d_in[0];   // [1, 2048, 2048]
    const float* gw  = (const float*)d_in[1];   // [64, 2048]
    const float* gup = (const float*)d_in[2];   // [64, 1536, 2048]
    const float* dwn = (const float*)d_in[3];   // [64, 2048, 768]
    const float* sim = (const float*)d_in[4];   // [64, 64]
    float* out = (float*)d_out;

    zero_kernel<<<1, 64>>>();
    router_kernel<<<T_TOK, 256>>>(x, gw);
    mapping_kernel<<<1, 64>>>(sim);
    reroute_kernel<<<(T_TOK * KTOP + 255) / 256, 256>>>();
    build_tiles_kernel<<<1, 1>>>();
    scatter_kernel<<<(T_TOK * KTOP + 255) / 256, 256>>>();
    gemm1_kernel<<<dim3(MAXMT, FI / 64), 128>>>(x, gup);
    gemm2_kernel<<<dim3(MAXMT, HD / 64), 128>>>(dwn);
    combine_kernel<<<T_TOK, 256>>>(out);
}

// round 8
// speedup vs baseline: 1.4474x; 1.0137x over previous
#include <cuda_runtime.h>
#include <math.h>
#include <stdint.h>

#define T_TOK 2048
#define NE 64
#define KTOP 8
#define SELK 4
#define HD 2048
#define FI 768
#define TWOF 1536
#define BM 64
#define MAXMT 320            // sum ceil(cnt/64) <= 16384/64 + 64
#define CAP 20480            // 16384 + 64*64 padded rows

// ---------------- scratch (device globals; no runtime allocation) ----------------
__device__ float d_topv[T_TOK * KTOP];
__device__ int   d_topi[T_TOK * KTOP];
__device__ int   d_rer[T_TOK * KTOP];
__device__ unsigned int d_pmask[2];
__device__ unsigned int d_smask[2];
__device__ int d_map[NE];
__device__ int d_counts[NE];
__device__ int d_padoff[NE];
__device__ int d_cursor[NE];
__device__ int d_tile_e[MAXMT];
__device__ int d_tile_base[MAXMT];
__device__ int d_tile_lim[MAXMT];
__device__ int d_nmt;
__device__ int d_totalpad;
__device__ int d_row_src[CAP];
__device__ float d_row_w[CAP];
__device__ int d_row_of[T_TOK * KTOP];
__device__ float d_hact[(size_t)CAP * FI];
__device__ float d_y[(size_t)CAP * HD];

// ---------------- fp16 helpers (legacy mma.sync path; tcgen05 unavailable:
// harness ptxas target is sm_103 without the 'a' suffix) ----------------------
__device__ __forceinline__ uint32_t packh2(float lo, float hi) {
    uint32_t u;
    asm("cvt.rn.f16x2.f32 %0, %1, %2;" : "=r"(u) : "f"(hi), "f"(lo));
    return u;
}
__device__ __forceinline__ uint2 cvt4h(float4 v) {
    return make_uint2(packh2(v.x, v.y), packh2(v.z, v.w));
}
__device__ __forceinline__ void mma_f16(float* c, const uint32_t* a, uint32_t b0, uint32_t b1) {
    asm volatile(
        "mma.sync.aligned.m16n8k16.row.col.f32.f16.f16.f32 "
        "{%0,%1,%2,%3}, {%4,%5,%6,%7}, {%8,%9}, {%0,%1,%2,%3};\n"
        : "+f"(c[0]), "+f"(c[1]), "+f"(c[2]), "+f"(c[3])
        : "r"(a[0]), "r"(a[1]), "r"(a[2]), "r"(a[3]), "r"(b0), "r"(b1));
}
__device__ __forceinline__ void ldsm4(uint32_t* r, uint32_t a) {
    asm volatile("ldmatrix.sync.aligned.m8n8.x4.shared.b16 {%0,%1,%2,%3}, [%4];"
                 : "=r"(r[0]), "=r"(r[1]), "=r"(r[2]), "=r"(r[3]) : "r"(a));
}
__device__ __forceinline__ uint32_t smem_u32(const void* p) {
    uint32_t a;
    asm("{ .reg .u64 t; cvta.to.shared.u64 t, %1; cvt.u32.u64 %0, t; }" : "=r"(a) : "l"(p));
    return a;
}

// ---------------- reset mutable state ----------------
__global__ void zero_kernel() {
    int i = threadIdx.x;
    if (i < NE) d_counts[i] = 0;
    if (i < 2) { d_pmask[i] = 0u; d_smask[i] = 0u; }
}

// ---------------- router ----------------
__global__ void router_kernel(const float* __restrict__ x, const float* __restrict__ gw) {
    __shared__ float sx[HD];
    __shared__ float sl[NE];
    int t = blockIdx.x;
    const float* xr = x + (size_t)t * HD;
    for (int i = threadIdx.x; i < HD; i += blockDim.x) sx[i] = xr[i];
    __syncthreads();

    int e   = threadIdx.x >> 2;
    int sub = threadIdx.x & 3;
    const float4* wp = (const float4*)(gw + (size_t)e * HD + sub * (HD / 4));
    const float4* xp = (const float4*)(sx + sub * (HD / 4));
    float s = 0.f;
#pragma unroll 4
    for (int i = 0; i < HD / 16; i++) {
        float4 a = xp[i]; float4 w = wp[i];
        s += a.x * w.x + a.y * w.y + a.z * w.z + a.w * w.w;
    }
    s += __shfl_xor_sync(0xffffffffu, s, 1);
    s += __shfl_xor_sync(0xffffffffu, s, 2);
    if (sub == 0) sl[e] = s;
    __syncthreads();

    if (threadIdx.x < 32) {
        int lane = threadIdx.x;
        float v0 = sl[lane], v1 = sl[lane + 32];
        float m = fmaxf(v0, v1);
        for (int off = 16; off; off >>= 1) m = fmaxf(m, __shfl_xor_sync(0xffffffffu, m, off));
        float e0 = expf(v0 - m), e1 = expf(v1 - m);
        float ss = e0 + e1;
        for (int off = 16; off; off >>= 1) ss += __shfl_xor_sync(0xffffffffu, ss, off);
        float p0 = e0 / ss, p1 = e1 / ss;

        float tv[KTOP]; int ti[KTOP];
#pragma unroll
        for (int k = 0; k < KTOP; k++) {
            float b; int bi;
            if (p0 >= p1) { b = p0; bi = lane; } else { b = p1; bi = lane + 32; }
            for (int off = 16; off; off >>= 1) {
                float ob = __shfl_xor_sync(0xffffffffu, b, off);
                int obi  = __shfl_xor_sync(0xffffffffu, bi, off);
                if (ob > b || (ob == b && obi < bi)) { b = ob; bi = obi; }
            }
            tv[k] = b; ti[k] = bi;
            if (bi < 32) { if (lane == bi) p0 = -1.f; }
            else         { if (lane == bi - 32) p1 = -1.f; }
        }
        if (lane == 0) {
            float tsum = 0.f;
#pragma unroll
            for (int k = 0; k < KTOP; k++) tsum += tv[k];
            tsum = fmaxf(tsum, 1e-12f);
#pragma unroll
            for (int k = 0; k < KTOP; k++) {
                d_topv[t * KTOP + k] = tv[k] / tsum;
                d_topi[t * KTOP + k] = ti[k];
                int b = ti[k];
                if (k < SELK) atomicOr(&d_pmask[b >> 5], 1u << (b & 31));
                else          atomicOr(&d_smask[b >> 5], 1u << (b & 31));
            }
        }
    }
}

// ---------------- SERE mapping ----------------
__global__ void mapping_kernel(const float* __restrict__ sim) {
    int e = threadIdx.x;
    if (e >= NE) return;
    unsigned pm0 = d_pmask[0], pm1 = d_pmask[1];
    unsigned sm0 = d_smask[0], sm1 = d_smask[1];
    bool prim = (e < 32) ? ((pm0 >> e) & 1) : ((pm1 >> (e - 32)) & 1);
    bool sec  = (e < 32) ? ((sm0 >> e) & 1) : ((sm1 >> (e - 32)) & 1);
    int best = 0; float bs = -INFINITY;
    for (int p = 0; p < NE; p++) {
        bool pp = (p < 32) ? ((pm0 >> p) & 1) : ((pm1 >> (p - 32)) & 1);
        if (!pp) continue;
        float v = (p == e) ? 1.0f : sim[e * NE + p];
        if (v > bs) { bs = v; best = p; }
    }
    int mp = e;
    if (sec && !prim && bs >= 0.5f) mp = best;
    d_map[e] = mp;
}

// ---------------- reroute + counts ----------------
__global__ void reroute_kernel() {
    int a = blockIdx.x * blockDim.x + threadIdx.x;
    if (a >= T_TOK * KTOP) return;
    int k = a & 7;
    int e0 = d_topi[a];
    int e = (k < SELK) ? e0 : d_map[e0];
    d_rer[a] = e;
    atomicAdd(&d_counts[e], 1);
}

// ---------------- tile table ----------------
__global__ void build_tiles_kernel() {
    if (threadIdx.x != 0 || blockIdx.x != 0) return;
    int off = 0, nt = 0;
    for (int e = 0; e < NE; e++) {
        d_padoff[e] = off;
        d_cursor[e] = 0;
        int c = d_counts[e];
        int mt = (c + BM - 1) / BM;
        for (int i = 0; i < mt; i++) {
            d_tile_e[nt] = e;
            d_tile_base[nt] = off + i * BM;
            int lm = c - i * BM; if (lm > BM) lm = BM;
            d_tile_lim[nt] = lm;
            nt++;
        }
        off += mt * BM;
    }
    d_nmt = nt;
    d_totalpad = off;
}

// ---------------- scatter ----------------
__global__ void scatter_kernel() {
    int a = blockIdx.x * blockDim.x + threadIdx.x;
    if (a >= T_TOK * KTOP) return;
    int e = d_rer[a];
    int pos = d_padoff[e] + atomicAdd(&d_cursor[e], 1);
    d_row_src[pos] = a >> 3;
    d_row_w[pos] = d_topv[a];
    d_row_of[a] = pos;
}

// ======================================================================
// GEMM1 (fp16 mma.sync m16n8k16, fp32 accum, ldmatrix frags) + fused SwiGLU.
// CTA: 64 token-rows x (64 gate cols + matching 64 up cols), 4 warps,
// warp tile 32 rows x 32 gate + 32 up cols. BK = 32 floats per stage.
// SMEM element = half2, row = 16 uints padded to 20 (conflict-free for LDSM).
// ======================================================================
__global__ __launch_bounds__(128) void gemm1_kernel(const float* __restrict__ x,
                                                    const float* __restrict__ gup) {
    int bx = blockIdx.x;
    if (bx >= d_nmt) return;
    int e = d_tile_e[bx], base = d_tile_base[bx], lim = d_tile_lim[bx];
    int n0 = blockIdx.y * 64;          // gate column base in [0, 768)

    __shared__ __align__(16) uint32_t As[2][64][20];    // 64 rows x 16 kpairs
    __shared__ __align__(16) uint32_t Bs[2][128][20];   // rows 0-63 gate, 64-127 up
    __shared__ int srow[64];

    int tid = threadIdx.x;
    if (tid < 64) srow[tid] = (tid < lim) ? d_row_src[base + tid] : -1;
    __syncthreads();

    int lkq = tid & 3;                 // quarter of 32 k-floats: 8 floats each
    int r0 = tid >> 2;                 // 0..31
    const float* aptr[2];
#pragma unroll
    for (int i = 0; i < 2; i++) {
        int s = srow[r0 + i * 32];
        aptr[i] = (s >= 0) ? (x + (size_t)s * HD + lkq * 8) : (const float*)0;
    }
    const float* bptr[4];
#pragma unroll
    for (int i = 0; i < 4; i++) {
        int row = r0 + i * 32;
        int br = (row < 64) ? (n0 + row) : (FI + n0 + (row - 64));
        bptr[i] = gup + ((size_t)e * TWOF + br) * HD + lkq * 8;
    }

    int warp = tid >> 5, lane = tid & 31;
    int wm = warp >> 1, wn = warp & 1;
    int g = lane >> 2, tg = lane & 3;

    // ldmatrix per-lane offsets (in uints)
    int offA = ((lane & 7) + ((lane >> 3) & 1) * 8) * 20 + (lane >> 4) * 4;
    int offB = ((lane & 7) + ((lane >> 4) & 1) * 8) * 20 + ((lane >> 3) & 1) * 4;
    uint32_t asb[2] = { smem_u32(&As[0][0][0]), smem_u32(&As[1][0][0]) };
    uint32_t bsb[2] = { smem_u32(&Bs[0][0][0]), smem_u32(&Bs[1][0][0]) };

    float cg[2][4][4] = {};
    float cu[2][4][4] = {};

    const float4 z4 = make_float4(0.f, 0.f, 0.f, 0.f);
    float4 ra[2][2], rb[4][2];
#pragma unroll
    for (int i = 0; i < 2; i++) {
        ra[i][0] = aptr[i] ? ((const float4*)aptr[i])[0] : z4;
        ra[i][1] = aptr[i] ? ((const float4*)aptr[i])[1] : z4;
    }
#pragma unroll
    for (int i = 0; i < 4; i++) {
        rb[i][0] = ((const float4*)bptr[i])[0];
        rb[i][1] = ((const float4*)bptr[i])[1];
    }
#pragma unroll
    for (int i = 0; i < 2; i++) {
        uint2 p0 = cvt4h(ra[i][0]), p1 = cvt4h(ra[i][1]);
        *(uint4*)&As[0][r0 + i * 32][lkq * 4] = make_uint4(p0.x, p0.y, p1.x, p1.y);
    }
#pragma unroll
    for (int i = 0; i < 4; i++) {
        uint2 p0 = cvt4h(rb[i][0]), p1 = cvt4h(rb[i][1]);
        *(uint4*)&Bs[0][r0 + i * 32][lkq * 4] = make_uint4(p0.x, p0.y, p1.x, p1.y);
    }
    __syncthreads();

    int buf = 0;
    const int NIT = HD / 32;           // 64
    for (int it = 0; it < NIT; it++) {
        if (it + 1 < NIT) {
            int kn = (it + 1) * 32;
#pragma unroll
            for (int i = 0; i < 2; i++) {
                ra[i][0] = aptr[i] ? ((const float4*)(aptr[i] + kn))[0] : z4;
                ra[i][1] = aptr[i] ? ((const float4*)(aptr[i] + kn))[1] : z4;
            }
#pragma unroll
            for (int i = 0; i < 4; i++) {
                rb[i][0] = ((const float4*)(bptr[i] + kn))[0];
                rb[i][1] = ((const float4*)(bptr[i] + kn))[1];
            }
        }
#pragma unroll
        for (int kk = 0; kk < 16; kk += 8) {           // two k16 steps per stage
            uint32_t af[2][4], bg[8], bu[8];
            ldsm4(af[0], asb[buf] + 4u * (offA + (wm * 32) * 20 + kk));
            ldsm4(af[1], asb[buf] + 4u * (offA + (wm * 32 + 16) * 20 + kk));
            ldsm4(bg + 0, bsb[buf] + 4u * (offB + (wn * 32) * 20 + kk));
            ldsm4(bg + 4, bsb[buf] + 4u * (offB + (wn * 32 + 16) * 20 + kk));
            ldsm4(bu + 0, bsb[buf] + 4u * (offB + (64 + wn * 32) * 20 + kk));
            ldsm4(bu + 4, bsb[buf] + 4u * (offB + (64 + wn * 32 + 16) * 20 + kk));
#pragma unroll
            for (int ni = 0; ni < 4; ni++) {
#pragma unroll
                for (int mi = 0; mi < 2; mi++) {
                    mma_f16(cg[mi][ni], af[mi], bg[ni * 2], bg[ni * 2 + 1]);
                    mma_f16(cu[mi][ni], af[mi], bu[ni * 2], bu[ni * 2 + 1]);
                }
            }
        }
        if (it + 1 < NIT) {
            int d = buf ^ 1;
#pragma unroll
            for (int i = 0; i < 2; i++) {
                uint2 p0 = cvt4h(ra[i][0]), p1 = cvt4h(ra[i][1]);
                *(uint4*)&As[d][r0 + i * 32][lkq * 4] = make_uint4(p0.x, p0.y, p1.x, p1.y);
            }
#pragma unroll
            for (int i = 0; i < 4; i++) {
                uint2 p0 = cvt4h(rb[i][0]), p1 = cvt4h(rb[i][1]);
                *(uint4*)&Bs[d][r0 + i * 32][lkq * 4] = make_uint4(p0.x, p0.y, p1.x, p1.y);
            }
        }
        __syncthreads();
        buf ^= 1;
    }

    // fused SwiGLU epilogue
#pragma unroll
    for (int mi = 0; mi < 2; mi++) {
#pragma unroll
        for (int half = 0; half < 2; half++) {
            int row = wm * 32 + mi * 16 + g + half * 8;
            if (row < lim) {
                float* dst = d_hact + (size_t)(base + row) * FI + n0 + wn * 32;
#pragma unroll
                for (int ni = 0; ni < 4; ni++) {
                    float g0 = cg[mi][ni][half * 2 + 0], g1 = cg[mi][ni][half * 2 + 1];
                    float u0 = cu[mi][ni][half * 2 + 0], u1 = cu[mi][ni][half * 2 + 1];
                    float h0 = g0 / (1.f + expf(-g0)) * u0;
                    float h1 = g1 / (1.f + expf(-g1)) * u1;
                    *(float2*)(dst + ni * 8 + tg * 2) = make_float2(h0, h1);
                }
            }
        }
    }
}

// ======================================================================
// GEMM2 (fp16 mma.sync, ldmatrix frags): y[r, n0:n0+64] = w[r] * (hact[r] @ down[e]^T)
// CTA: 64 rows x 64 cols, 4 warps, warp tile 32x32. BK = 32 floats.
// ======================================================================
__global__ __launch_bounds__(128) void gemm2_kernel(const float* __restrict__ dwn) {
    int bx = blockIdx.x;
    if (bx >= d_nmt) return;
    int e = d_tile_e[bx], base = d_tile_base[bx], lim = d_tile_lim[bx];
    int n0 = blockIdx.y * 64;          // output column in [0, 2048)

    __shared__ __align__(16) uint32_t As[2][64][20];
    __shared__ __align__(16) uint32_t Bs[2][64][20];

    int tid = threadIdx.x;
    int lkq = tid & 3;
    int r0 = tid >> 2;
    const float* aptr[2];
#pragma unroll
    for (int i = 0; i < 2; i++)
        aptr[i] = d_hact + (size_t)(base + r0 + i * 32) * FI + lkq * 8;
    const float* bptr[2];
#pragma unroll
    for (int i = 0; i < 2; i++)
        bptr[i] = dwn + ((size_t)e * HD + n0 + r0 + i * 32) * FI + lkq * 8;

    int warp = tid >> 5, lane = tid & 31;
    int wm = warp >> 1, wn = warp & 1;
    int g = lane >> 2, tg = lane & 3;

    int offA = ((lane & 7) + ((lane >> 3) & 1) * 8) * 20 + (lane >> 4) * 4;
    int offB = ((lane & 7) + ((lane >> 4) & 1) * 8) * 20 + ((lane >> 3) & 1) * 4;
    uint32_t asb[2] = { smem_u32(&As[0][0][0]), smem_u32(&As[1][0][0]) };
    uint32_t bsb[2] = { smem_u32(&Bs[0][0][0]), smem_u32(&Bs[1][0][0]) };

    float cc[2][4][4] = {};

    float4 ra[2][2], rb[2][2];
#pragma unroll
    for (int i = 0; i < 2; i++) {
        ra[i][0] = ((const float4*)aptr[i])[0];
        ra[i][1] = ((const float4*)aptr[i])[1];
        rb[i][0] = ((const float4*)bptr[i])[0];
        rb[i][1] = ((const float4*)bptr[i])[1];
    }
#pragma unroll
    for (int i = 0; i < 2; i++) {
        uint2 a0 = cvt4h(ra[i][0]), a1 = cvt4h(ra[i][1]);
        uint2 b0 = cvt4h(rb[i][0]), b1 = cvt4h(rb[i][1]);
        *(uint4*)&As[0][r0 + i * 32][lkq * 4] = make_uint4(a0.x, a0.y, a1.x, a1.y);
        *(uint4*)&Bs[0][r0 + i * 32][lkq * 4] = make_uint4(b0.x, b0.y, b1.x, b1.y);
    }
    __syncthreads();

    int buf = 0;
    const int NIT = FI / 32;           // 24
    for (int it = 0; it < NIT; it++) {
        if (it + 1 < NIT) {
            int kn = (it + 1) * 32;
#pragma unroll
            for (int i = 0; i < 2; i++) {
                ra[i][0] = ((const float4*)(aptr[i] + kn))[0];
                ra[i][1] = ((const float4*)(aptr[i] + kn))[1];
                rb[i][0] = ((const float4*)(bptr[i] + kn))[0];
                rb[i][1] = ((const float4*)(bptr[i] + kn))[1];
            }
        }
#pragma unroll
        for (int kk = 0; kk < 16; kk += 8) {
            uint32_t af[2][4], bb[8];
            ldsm4(af[0], asb[buf] + 4u * (offA + (wm * 32) * 20 + kk));
            ldsm4(af[1], asb[buf] + 4u * (offA + (wm * 32 + 16) * 20 + kk));
            ldsm4(bb + 0, bsb[buf] + 4u * (offB + (wn * 32) * 20 + kk));
            ldsm4(bb + 4, bsb[buf] + 4u * (offB + (wn * 32 + 16) * 20 + kk));
#pragma unroll
            for (int ni = 0; ni < 4; ni++) {
#pragma unroll
                for (int mi = 0; mi < 2; mi++)
                    mma_f16(cc[mi][ni], af[mi], bb[ni * 2], bb[ni * 2 + 1]);
            }
        }
        if (it + 1 < NIT) {
            int d = buf ^ 1;
#pragma unroll
            for (int i = 0; i < 2; i++) {
                uint2 a0 = cvt4h(ra[i][0]), a1 = cvt4h(ra[i][1]);
                uint2 b0 = cvt4h(rb[i][0]), b1 = cvt4h(rb[i][1]);
                *(uint4*)&As[d][r0 + i * 32][lkq * 4] = make_uint4(a0.x, a0.y, a1.x, a1.y);
                *(uint4*)&Bs[d][r0 + i * 32][lkq * 4] = make_uint4(b0.x, b0.y, b1.x, b1.y);
            }
        }
        __syncthreads();
        buf ^= 1;
    }

#pragma unroll
    for (int mi = 0; mi < 2; mi++) {
#pragma unroll
        for (int half = 0; half < 2; half++) {
            int row = wm * 32 + mi * 16 + g + half * 8;
            if (row < lim) {
                float w = d_row_w[base + row];
                float* dst = d_y + (size_t)(base + row) * HD + n0 + wn * 32;
#pragma unroll
                for (int ni = 0; ni < 4; ni++) {
                    float v0 = cc[mi][ni][half * 2 + 0] * w;
                    float v1 = cc[mi][ni][half * 2 + 1] * w;
                    *(float2*)(dst + ni * 8 + tg * 2) = make_float2(v0, v1);
                }
            }
        }
    }
}

// ---------------- deterministic combine ----------------
__global__ void combine_kernel(float* __restrict__ out) {
    int t = blockIdx.x;
    __shared__ int rows[KTOP];
    if (threadIdx.x < KTOP) rows[threadIdx.x] = d_row_of[t * KTOP + threadIdx.x];
    __syncthreads();
    for (int h = threadIdx.x; h < HD; h += blockDim.x) {
        float s = 0.f;
#pragma unroll
        for (int k = 0; k < KTOP; k++) s += d_y[(size_t)rows[k] * HD + h];
        out[(size_t)t * HD + h] = s;
    }
}

// ---------------- launch ----------------
extern "C" void kernel_launch(void* const* d_in, const int* in_sizes, int n_in,
                              void* d_out, int out_size) {
    const float* x   = (const float*)d_in[0];   // [1, 2048, 2048]
    const float* gw  = (const float*)d_in[1];   // [64, 2048]
    const float* gup = (const float*)d_in[2];   // [64, 1536, 2048]
    const float* dwn = (const float*)d_in[3];   // [64, 2048, 768]
    const float* sim = (const float*)d_in[4];   // [64, 64]
    float* out = (float*)d_out;

    zero_kernel<<<1, 64>>>();
    router_kernel<<<T_TOK, 256>>>(x, gw);
    mapping_kernel<<<1, 64>>>(sim);
    reroute_kernel<<<(T_TOK * KTOP + 255) / 256, 256>>>();
    build_tiles_kernel<<<1, 1>>>();
    scatter_kernel<<<(T_TOK * KTOP + 255) / 256, 256>>>();
    gemm1_kernel<<<dim3(MAXMT, FI / 64), 128>>>(x, gup);
    gemm2_kernel<<<dim3(MAXMT, HD / 64), 128>>>(dwn);
    combine_kernel<<<T_TOK, 256>>>(out);
}

// round 9
// speedup vs baseline: 1.6035x; 1.1078x over previous
#include <cuda_runtime.h>
#include <math.h>
#include <stdint.h>

#define T_TOK 2048
#define NE 64
#define KTOP 8
#define SELK 4
#define HD 2048
#define FI 768
#define TWOF 1536
#define BM 64
#define MAXMT 320            // sum ceil(cnt/64) <= 16384/64 + 64
#define CAP 20480            // 16384 + 64*64 padded rows

// ---------------- scratch (device globals; no runtime allocation) ----------------
__device__ float d_topv[T_TOK * KTOP];
__device__ int   d_topi[T_TOK * KTOP];
__device__ int   d_rer[T_TOK * KTOP];
__device__ int d_tile_e[MAXMT];
__device__ int d_tile_base[MAXMT];
__device__ int d_tile_lim[MAXMT];
__device__ int d_nmt;
__device__ int d_counts[NE];
__device__ int d_map[NE];
__device__ int d_row_src[CAP];
__device__ float d_row_w[CAP];
__device__ int d_row_of[T_TOK * KTOP];
__device__ float d_hact[(size_t)CAP * FI];
__device__ float d_y[(size_t)CAP * HD];

// ---------------- fp16 helpers (legacy mma.sync path; tcgen05 unavailable:
// harness ptxas target is sm_103 without the 'a' suffix) ----------------------
__device__ __forceinline__ uint32_t packh2(float lo, float hi) {
    uint32_t u;
    asm("cvt.rn.f16x2.f32 %0, %1, %2;" : "=r"(u) : "f"(hi), "f"(lo));
    return u;
}
__device__ __forceinline__ uint2 cvt4h(float4 v) {
    return make_uint2(packh2(v.x, v.y), packh2(v.z, v.w));
}
__device__ __forceinline__ void mma_f16(float* c, const uint32_t* a, uint32_t b0, uint32_t b1) {
    asm volatile(
        "mma.sync.aligned.m16n8k16.row.col.f32.f16.f16.f32 "
        "{%0,%1,%2,%3}, {%4,%5,%6,%7}, {%8,%9}, {%0,%1,%2,%3};\n"
        : "+f"(c[0]), "+f"(c[1]), "+f"(c[2]), "+f"(c[3])
        : "r"(a[0]), "r"(a[1]), "r"(a[2]), "r"(a[3]), "r"(b0), "r"(b1));
}
__device__ __forceinline__ void ldsm4(uint32_t* r, uint32_t a) {
    asm volatile("ldmatrix.sync.aligned.m8n8.x4.shared.b16 {%0,%1,%2,%3}, [%4];"
                 : "=r"(r[0]), "=r"(r[1]), "=r"(r[2]), "=r"(r[3]) : "r"(a));
}
__device__ __forceinline__ uint32_t smem_u32(const void* p) {
    uint32_t a;
    asm("{ .reg .u64 t; cvta.to.shared.u64 t, %1; cvt.u32.u64 %0, t; }" : "=r"(a) : "l"(p));
    return a;
}

// ---------------- router: 4 tokens per block (gw L2 traffic / 4) ----------------
__global__ __launch_bounds__(256) void router_kernel(const float* __restrict__ x,
                                                     const float* __restrict__ gw) {
    __shared__ float sx[4][HD];        // 32 KB
    __shared__ float sl[4][NE];
    int t0 = blockIdx.x * 4;
    int tid = threadIdx.x;
    for (int i = tid; i < 4 * HD; i += 256)
        ((float*)sx)[i] = x[(size_t)t0 * HD + i];
    __syncthreads();

    int e   = tid >> 2;                // 0..63
    int sub = tid & 3;                 // quarter of H
    const float4* wp = (const float4*)(gw + (size_t)e * HD + sub * (HD / 4));
    float s0 = 0.f, s1 = 0.f, s2 = 0.f, s3 = 0.f;
    const float4* xp0 = (const float4*)(sx[0] + sub * (HD / 4));
    const float4* xp1 = (const float4*)(sx[1] + sub * (HD / 4));
    const float4* xp2 = (const float4*)(sx[2] + sub * (HD / 4));
    const float4* xp3 = (const float4*)(sx[3] + sub * (HD / 4));
#pragma unroll 4
    for (int i = 0; i < HD / 16; i++) {
        float4 w = wp[i];
        float4 a0 = xp0[i], a1 = xp1[i], a2 = xp2[i], a3 = xp3[i];
        s0 += a0.x * w.x + a0.y * w.y + a0.z * w.z + a0.w * w.w;
        s1 += a1.x * w.x + a1.y * w.y + a1.z * w.z + a1.w * w.w;
        s2 += a2.x * w.x + a2.y * w.y + a2.z * w.z + a2.w * w.w;
        s3 += a3.x * w.x + a3.y * w.y + a3.z * w.z + a3.w * w.w;
    }
    s0 += __shfl_xor_sync(0xffffffffu, s0, 1); s0 += __shfl_xor_sync(0xffffffffu, s0, 2);
    s1 += __shfl_xor_sync(0xffffffffu, s1, 1); s1 += __shfl_xor_sync(0xffffffffu, s1, 2);
    s2 += __shfl_xor_sync(0xffffffffu, s2, 1); s2 += __shfl_xor_sync(0xffffffffu, s2, 2);
    s3 += __shfl_xor_sync(0xffffffffu, s3, 1); s3 += __shfl_xor_sync(0xffffffffu, s3, 2);
    if (sub == 0) { sl[0][e] = s0; sl[1][e] = s1; sl[2][e] = s2; sl[3][e] = s3; }
    __syncthreads();

    int wrp = tid >> 5;
    if (wrp < 4) {                     // warp w handles token t0+w
        int lane = tid & 31;
        int t = t0 + wrp;
        float v0 = sl[wrp][lane], v1 = sl[wrp][lane + 32];
        float m = fmaxf(v0, v1);
        for (int off = 16; off; off >>= 1) m = fmaxf(m, __shfl_xor_sync(0xffffffffu, m, off));
        float e0 = expf(v0 - m), e1 = expf(v1 - m);
        float ss = e0 + e1;
        for (int off = 16; off; off >>= 1) ss += __shfl_xor_sync(0xffffffffu, ss, off);
        float p0 = e0 / ss, p1 = e1 / ss;

        float tv[KTOP]; int ti[KTOP];
#pragma unroll
        for (int k = 0; k < KTOP; k++) {
            float b; int bi;
            if (p0 >= p1) { b = p0; bi = lane; } else { b = p1; bi = lane + 32; }
            for (int off = 16; off; off >>= 1) {
                float ob = __shfl_xor_sync(0xffffffffu, b, off);
                int obi  = __shfl_xor_sync(0xffffffffu, bi, off);
                if (ob > b || (ob == b && obi < bi)) { b = ob; bi = obi; }
            }
            tv[k] = b; ti[k] = bi;
            if (bi < 32) { if (lane == bi) p0 = -1.f; }
            else         { if (lane == bi - 32) p1 = -1.f; }
        }
        if (lane == 0) {
            float tsum = 0.f;
#pragma unroll
            for (int k = 0; k < KTOP; k++) tsum += tv[k];
            tsum = fmaxf(tsum, 1e-12f);
#pragma unroll
            for (int k = 0; k < KTOP; k++) {
                d_topv[t * KTOP + k] = tv[k] / tsum;
                d_topi[t * KTOP + k] = ti[k];
            }
        }
    }
}

// ---------------- setup: masks -> SERE mapping -> reroute -> counts (one block) ----
__global__ __launch_bounds__(1024) void setup_kernel(const float* __restrict__ sim) {
    __shared__ unsigned pm[2], smk[2];
    __shared__ int cnts[NE], maps[NE];
    int tid = threadIdx.x;
    if (tid < 2) { pm[tid] = 0u; smk[tid] = 0u; }
    if (tid < NE) cnts[tid] = 0;
    __syncthreads();

    for (int a = tid; a < T_TOK * KTOP; a += 1024) {
        int e0 = d_topi[a];
        if ((a & 7) < SELK) atomicOr(&pm[e0 >> 5], 1u << (e0 & 31));
        else                atomicOr(&smk[e0 >> 5], 1u << (e0 & 31));
    }
    __syncthreads();

    if (tid < NE) {
        int e = tid;
        unsigned pm0 = pm[0], pm1 = pm[1];
        bool prim = (e < 32) ? ((pm0 >> e) & 1) : ((pm1 >> (e - 32)) & 1);
        bool sec  = (e < 32) ? ((smk[0] >> e) & 1) : ((smk[1] >> (e - 32)) & 1);
        int best = 0; float bs = -INFINITY;
        for (int p = 0; p < NE; p++) {
            bool pp = (p < 32) ? ((pm0 >> p) & 1) : ((pm1 >> (p - 32)) & 1);
            if (!pp) continue;
            float v = (p == e) ? 1.0f : sim[e * NE + p];
            if (v > bs) { bs = v; best = p; }
        }
        int mp = e;
        if (sec && !prim && bs >= 0.5f) mp = best;
        maps[e] = mp;
        d_map[e] = mp;
    }
    __syncthreads();

    for (int a = tid; a < T_TOK * KTOP; a += 1024) {
        int e0 = d_topi[a];
        int e = ((a & 7) < SELK) ? e0 : maps[e0];
        d_rer[a] = e;
        atomicAdd(&cnts[e], 1);
    }
    __syncthreads();
    if (tid < NE) d_counts[tid] = cnts[tid];
}

// ---------------- tile table + scatter (one block) ----------------
__global__ __launch_bounds__(1024) void tilescatter_kernel() {
    __shared__ int poff[NE];
    __shared__ int cur[NE];
    int tid = threadIdx.x;
    if (tid == 0) {
        int off = 0, nt = 0;
        for (int e = 0; e < NE; e++) {
            poff[e] = off;
            int c = d_counts[e];
            int mt = (c + BM - 1) / BM;
            for (int i = 0; i < mt; i++) {
                d_tile_e[nt] = e;
                d_tile_base[nt] = off + i * BM;
                int lm = c - i * BM; if (lm > BM) lm = BM;
                d_tile_lim[nt] = lm;
                nt++;
            }
            off += mt * BM;
        }
        d_nmt = nt;
    }
    if (tid < NE) cur[tid] = 0;
    __syncthreads();

    for (int a = tid; a < T_TOK * KTOP; a += 1024) {
        int e = d_rer[a];
        int pos = poff[e] + atomicAdd(&cur[e], 1);
        d_row_src[pos] = a >> 3;
        d_row_w[pos] = d_topv[a];
        d_row_of[a] = pos;
    }
}

// ======================================================================
// GEMM1 (fp16 mma.sync m16n8k16, fp32 accum, ldmatrix frags) + fused SwiGLU.
// CTA: 64 token-rows x (64 gate cols + matching 64 up cols), 4 warps,
// warp tile 32 rows x 32 gate + 32 up cols. BK = 32 floats per stage.
// ======================================================================
__global__ __launch_bounds__(128) void gemm1_kernel(const float* __restrict__ x,
                                                    const float* __restrict__ gup) {
    int bx = blockIdx.x;
    if (bx >= d_nmt) return;
    int e = d_tile_e[bx], base = d_tile_base[bx], lim = d_tile_lim[bx];
    int n0 = blockIdx.y * 64;          // gate column base in [0, 768)

    __shared__ __align__(16) uint32_t As[2][64][20];    // 64 rows x 16 kpairs
    __shared__ __align__(16) uint32_t Bs[2][128][20];   // rows 0-63 gate, 64-127 up
    __shared__ int srow[64];

    int tid = threadIdx.x;
    if (tid < 64) srow[tid] = (tid < lim) ? d_row_src[base + tid] : -1;
    __syncthreads();

    int lkq = tid & 3;
    int r0 = tid >> 2;
    const float* aptr[2];
#pragma unroll
    for (int i = 0; i < 2; i++) {
        int s = srow[r0 + i * 32];
        aptr[i] = (s >= 0) ? (x + (size_t)s * HD + lkq * 8) : (const float*)0;
    }
    const float* bptr[4];
#pragma unroll
    for (int i = 0; i < 4; i++) {
        int row = r0 + i * 32;
        int br = (row < 64) ? (n0 + row) : (FI + n0 + (row - 64));
        bptr[i] = gup + ((size_t)e * TWOF + br) * HD + lkq * 8;
    }

    int warp = tid >> 5, lane = tid & 31;
    int wm = warp >> 1, wn = warp & 1;
    int g = lane >> 2, tg = lane & 3;

    int offA = ((lane & 7) + ((lane >> 3) & 1) * 8) * 20 + (lane >> 4) * 4;
    int offB = ((lane & 7) + ((lane >> 4) & 1) * 8) * 20 + ((lane >> 3) & 1) * 4;
    uint32_t asb[2] = { smem_u32(&As[0][0][0]), smem_u32(&As[1][0][0]) };
    uint32_t bsb[2] = { smem_u32(&Bs[0][0][0]), smem_u32(&Bs[1][0][0]) };

    float cg[2][4][4] = {};
    float cu[2][4][4] = {};

    const float4 z4 = make_float4(0.f, 0.f, 0.f, 0.f);
    float4 ra[2][2], rb[4][2];
#pragma unroll
    for (int i = 0; i < 2; i++) {
        ra[i][0] = aptr[i] ? ((const float4*)aptr[i])[0] : z4;
        ra[i][1] = aptr[i] ? ((const float4*)aptr[i])[1] : z4;
    }
#pragma unroll
    for (int i = 0; i < 4; i++) {
        rb[i][0] = ((const float4*)bptr[i])[0];
        rb[i][1] = ((const float4*)bptr[i])[1];
    }
#pragma unroll
    for (int i = 0; i < 2; i++) {
        uint2 p0 = cvt4h(ra[i][0]), p1 = cvt4h(ra[i][1]);
        *(uint4*)&As[0][r0 + i * 32][lkq * 4] = make_uint4(p0.x, p0.y, p1.x, p1.y);
    }
#pragma unroll
    for (int i = 0; i < 4; i++) {
        uint2 p0 = cvt4h(rb[i][0]), p1 = cvt4h(rb[i][1]);
        *(uint4*)&Bs[0][r0 + i * 32][lkq * 4] = make_uint4(p0.x, p0.y, p1.x, p1.y);
    }
    __syncthreads();

    int buf = 0;
    const int NIT = HD / 32;           // 64
    for (int it = 0; it < NIT; it++) {
        if (it + 1 < NIT) {
            int kn = (it + 1) * 32;
#pragma unroll
            for (int i = 0; i < 2; i++) {
                ra[i][0] = aptr[i] ? ((const float4*)(aptr[i] + kn))[0] : z4;
                ra[i][1] = aptr[i] ? ((const float4*)(aptr[i] + kn))[1] : z4;
            }
#pragma unroll
            for (int i = 0; i < 4; i++) {
                rb[i][0] = ((const float4*)(bptr[i] + kn))[0];
                rb[i][1] = ((const float4*)(bptr[i] + kn))[1];
            }
        }
#pragma unroll
        for (int kk = 0; kk < 16; kk += 8) {
            uint32_t af[2][4], bg[8], bu[8];
            ldsm4(af[0], asb[buf] + 4u * (offA + (wm * 32) * 20 + kk));
            ldsm4(af[1], asb[buf] + 4u * (offA + (wm * 32 + 16) * 20 + kk));
            ldsm4(bg + 0, bsb[buf] + 4u * (offB + (wn * 32) * 20 + kk));
            ldsm4(bg + 4, bsb[buf] + 4u * (offB + (wn * 32 + 16) * 20 + kk));
            ldsm4(bu + 0, bsb[buf] + 4u * (offB + (64 + wn * 32) * 20 + kk));
            ldsm4(bu + 4, bsb[buf] + 4u * (offB + (64 + wn * 32 + 16) * 20 + kk));
#pragma unroll
            for (int ni = 0; ni < 4; ni++) {
#pragma unroll
                for (int mi = 0; mi < 2; mi++) {
                    mma_f16(cg[mi][ni], af[mi], bg[ni * 2], bg[ni * 2 + 1]);
                    mma_f16(cu[mi][ni], af[mi], bu[ni * 2], bu[ni * 2 + 1]);
                }
            }
        }
        if (it + 1 < NIT) {
            int d = buf ^ 1;
#pragma unroll
            for (int i = 0; i < 2; i++) {
                uint2 p0 = cvt4h(ra[i][0]), p1 = cvt4h(ra[i][1]);
                *(uint4*)&As[d][r0 + i * 32][lkq * 4] = make_uint4(p0.x, p0.y, p1.x, p1.y);
            }
#pragma unroll
            for (int i = 0; i < 4; i++) {
                uint2 p0 = cvt4h(rb[i][0]), p1 = cvt4h(rb[i][1]);
                *(uint4*)&Bs[d][r0 + i * 32][lkq * 4] = make_uint4(p0.x, p0.y, p1.x, p1.y);
            }
        }
        __syncthreads();
        buf ^= 1;
    }

    // fused SwiGLU epilogue
#pragma unroll
    for (int mi = 0; mi < 2; mi++) {
#pragma unroll
        for (int half = 0; half < 2; half++) {
            int row = wm * 32 + mi * 16 + g + half * 8;
            if (row < lim) {
                float* dst = d_hact + (size_t)(base + row) * FI + n0 + wn * 32;
#pragma unroll
                for (int ni = 0; ni < 4; ni++) {
                    float g0 = cg[mi][ni][half * 2 + 0], g1 = cg[mi][ni][half * 2 + 1];
                    float u0 = cu[mi][ni][half * 2 + 0], u1 = cu[mi][ni][half * 2 + 1];
                    float h0 = g0 / (1.f + expf(-g0)) * u0;
                    float h1 = g1 / (1.f + expf(-g1)) * u1;
                    *(float2*)(dst + ni * 8 + tg * 2) = make_float2(h0, h1);
                }
            }
        }
    }
}

// ======================================================================
// GEMM2 (fp16 mma.sync, ldmatrix frags): y[r, n0:n0+64] = w[r] * (hact[r] @ down[e]^T)
// ======================================================================
__global__ __launch_bounds__(128) void gemm2_kernel(const float* __restrict__ dwn) {
    int bx = blockIdx.x;
    if (bx >= d_nmt) return;
    int e = d_tile_e[bx], base = d_tile_base[bx], lim = d_tile_lim[bx];
    int n0 = blockIdx.y * 64;

    __shared__ __align__(16) uint32_t As[2][64][20];
    __shared__ __align__(16) uint32_t Bs[2][64][20];

    int tid = threadIdx.x;
    int lkq = tid & 3;
    int r0 = tid >> 2;
    const float* aptr[2];
#pragma unroll
    for (int i = 0; i < 2; i++)
        aptr[i] = d_hact + (size_t)(base + r0 + i * 32) * FI + lkq * 8;
    const float* bptr[2];
#pragma unroll
    for (int i = 0; i < 2; i++)
        bptr[i] = dwn + ((size_t)e * HD + n0 + r0 + i * 32) * FI + lkq * 8;

    int warp = tid >> 5, lane = tid & 31;
    int wm = warp >> 1, wn = warp & 1;
    int g = lane >> 2, tg = lane & 3;

    int offA = ((lane & 7) + ((lane >> 3) & 1) * 8) * 20 + (lane >> 4) * 4;
    int offB = ((lane & 7) + ((lane >> 4) & 1) * 8) * 20 + ((lane >> 3) & 1) * 4;
    uint32_t asb[2] = { smem_u32(&As[0][0][0]), smem_u32(&As[1][0][0]) };
    uint32_t bsb[2] = { smem_u32(&Bs[0][0][0]), smem_u32(&Bs[1][0][0]) };

    float cc[2][4][4] = {};

    float4 ra[2][2], rb[2][2];
#pragma unroll
    for (int i = 0; i < 2; i++) {
        ra[i][0] = ((const float4*)aptr[i])[0];
        ra[i][1] = ((const float4*)aptr[i])[1];
        rb[i][0] = ((const float4*)bptr[i])[0];
        rb[i][1] = ((const float4*)bptr[i])[1];
    }
#pragma unroll
    for (int i = 0; i < 2; i++) {
        uint2 a0 = cvt4h(ra[i][0]), a1 = cvt4h(ra[i][1]);
        uint2 b0 = cvt4h(rb[i][0]), b1 = cvt4h(rb[i][1]);
        *(uint4*)&As[0][r0 + i * 32][lkq * 4] = make_uint4(a0.x, a0.y, a1.x, a1.y);
        *(uint4*)&Bs[0][r0 + i * 32][lkq * 4] = make_uint4(b0.x, b0.y, b1.x, b1.y);
    }
    __syncthreads();

    int buf = 0;
    const int NIT = FI / 32;           // 24
    for (int it = 0; it < NIT; it++) {
        if (it + 1 < NIT) {
            int kn = (it + 1) * 32;
#pragma unroll
            for (int i = 0; i < 2; i++) {
                ra[i][0] = ((const float4*)(aptr[i] + kn))[0];
                ra[i][1] = ((const float4*)(aptr[i] + kn))[1];
                rb[i][0] = ((const float4*)(bptr[i] + kn))[0];
                rb[i][1] = ((const float4*)(bptr[i] + kn))[1];
            }
        }
#pragma unroll
        for (int kk = 0; kk < 16; kk += 8) {
            uint32_t af[2][4], bb[8];
            ldsm4(af[0], asb[buf] + 4u * (offA + (wm * 32) * 20 + kk));
            ldsm4(af[1], asb[buf] + 4u * (offA + (wm * 32 + 16) * 20 + kk));
            ldsm4(bb + 0, bsb[buf] + 4u * (offB + (wn * 32) * 20 + kk));
            ldsm4(bb + 4, bsb[buf] + 4u * (offB + (wn * 32 + 16) * 20 + kk));
#pragma unroll
            for (int ni = 0; ni < 4; ni++) {
#pragma unroll
                for (int mi = 0; mi < 2; mi++)
                    mma_f16(cc[mi][ni], af[mi], bb[ni * 2], bb[ni * 2 + 1]);
            }
        }
        if (it + 1 < NIT) {
            int d = buf ^ 1;
#pragma unroll
            for (int i = 0; i < 2; i++) {
                uint2 a0 = cvt4h(ra[i][0]), a1 = cvt4h(ra[i][1]);
                uint2 b0 = cvt4h(rb[i][0]), b1 = cvt4h(rb[i][1]);
                *(uint4*)&As[d][r0 + i * 32][lkq * 4] = make_uint4(a0.x, a0.y, a1.x, a1.y);
                *(uint4*)&Bs[d][r0 + i * 32][lkq * 4] = make_uint4(b0.x, b0.y, b1.x, b1.y);
            }
        }
        __syncthreads();
        buf ^= 1;
    }

#pragma unroll
    for (int mi = 0; mi < 2; mi++) {
#pragma unroll
        for (int half = 0; half < 2; half++) {
            int row = wm * 32 + mi * 16 + g + half * 8;
            if (row < lim) {
                float w = d_row_w[base + row];
                float* dst = d_y + (size_t)(base + row) * HD + n0 + wn * 32;
#pragma unroll
                for (int ni = 0; ni < 4; ni++) {
                    float v0 = cc[mi][ni][half * 2 + 0] * w;
                    float v1 = cc[mi][ni][half * 2 + 1] * w;
                    *(float2*)(dst + ni * 8 + tg * 2) = make_float2(v0, v1);
                }
            }
        }
    }
}

// ---------------- deterministic combine ----------------
__global__ void combine_kernel(float* __restrict__ out) {
    int t = blockIdx.x;
    __shared__ int rows[KTOP];
    if (threadIdx.x < KTOP) rows[threadIdx.x] = d_row_of[t * KTOP + threadIdx.x];
    __syncthreads();
    for (int h = threadIdx.x; h < HD; h += blockDim.x) {
        float s = 0.f;
#pragma unroll
        for (int k = 0; k < KTOP; k++) s += d_y[(size_t)rows[k] * HD + h];
        out[(size_t)t * HD + h] = s;
    }
}

// ---------------- launch ----------------
extern "C" void kernel_launch(void* const* d_in, const int* in_sizes, int n_in,
                              void* d_out, int out_size) {
    const float* x   = (const float*)d_in[0];   // [1, 2048, 2048]
    const float* gw  = (const float*)d_in[1];   // [64, 2048]
    const float* gup = (const float*)d_in[2];   // [64, 1536, 2048]
    const float* dwn = (const float*)d_in[3];   // [64, 2048, 768]
    const float* sim = (const float*)d_in[4];   // [64, 64]
    float* out = (float*)d_out;

    router_kernel<<<T_TOK / 4, 256>>>(x, gw);          // launch 0
    setup_kernel<<<1, 1024>>>(sim);                    // launch 1
    tilescatter_kernel<<<1, 1024>>>();                 // launch 2
    gemm1_kernel<<<dim3(MAXMT, FI / 64), 128>>>(x, gup);   // launch 3 (ncu target)
    gemm2_kernel<<<dim3(MAXMT, HD / 64), 128>>>(dwn);      // launch 4
    combine_kernel<<<T_TOK, 256>>>(out);               // launch 5
}